// round 16
// baseline (speedup 1.0000x reference)
#include <cuda_runtime.h>
#include <cuda_bf16.h>
#include <cstdint>
#include <math.h>

#define H_ 192
#define W_ 192
#define C_ 256
#define C4_ 1024
#define N_ 36864
#define E_ 294912
#define K_ 289

// ======================= PTX helpers (base sm_103 target: NO tcgen05) ==========
__device__ __forceinline__ uint32_t smem_to_u32(const void* p) {
    uint32_t a;
    asm("{ .reg .u64 t; cvta.to.shared.u64 t, %1; cvt.u32.u64 %0, t; }" : "=r"(a) : "l"(p));
    return a;
}
__device__ __forceinline__ void cpa16(uint32_t dst, const void* src) {
    asm volatile("cp.async.cg.shared.global [%0], [%1], 16;" :: "r"(dst), "l"(src) : "memory");
}
__device__ __forceinline__ void cpa_commit() {
    asm volatile("cp.async.commit_group;" ::: "memory");
}
template<int NN>
__device__ __forceinline__ void cpa_wait() {
    asm volatile("cp.async.wait_group %0;" :: "n"(NN) : "memory");
}
__device__ __forceinline__ void ldm_x4(uint32_t* r, uint32_t addr) {
    asm volatile("ldmatrix.sync.aligned.m8n8.x4.shared.b16 {%0,%1,%2,%3}, [%4];"
        : "=r"(r[0]), "=r"(r[1]), "=r"(r[2]), "=r"(r[3]) : "r"(addr));
}
__device__ __forceinline__ void ldm_x2(uint32_t* r, uint32_t addr) {
    asm volatile("ldmatrix.sync.aligned.m8n8.x2.shared.b16 {%0,%1}, [%2];"
        : "=r"(r[0]), "=r"(r[1]) : "r"(addr));
}
__device__ __forceinline__ void mma_bf16(float* d, const uint32_t* a, const uint32_t* b) {
    asm volatile("mma.sync.aligned.m16n8k16.row.col.f32.bf16.bf16.f32 "
        "{%0,%1,%2,%3}, {%4,%5,%6,%7}, {%8,%9}, {%0,%1,%2,%3};"
        : "+f"(d[0]), "+f"(d[1]), "+f"(d[2]), "+f"(d[3])
        : "r"(a[0]), "r"(a[1]), "r"(a[2]), "r"(a[3]), "r"(b[0]), "r"(b[1]));
}
__device__ __forceinline__ void red_v4(float* p, float a, float b, float c, float d) {
    asm volatile("red.global.add.v4.f32 [%0], {%1,%2,%3,%4};"
        :: "l"(p), "f"(a), "f"(b), "f"(c), "f"(d) : "memory");
}
#define SWZ(o) ((o) ^ (((o) >> 3) & 0x70))

// ======================= scratch =======================
__device__ __align__(128) float g_img[(size_t)C_ * N_];
__device__ __align__(128) float g_tb [(size_t)C_ * N_];
__device__ __align__(128) float g_t2 [(size_t)C_ * N_];
__device__ __align__(128) float g_big[(size_t)C4_ * N_];   // dw3 out: 2x bf16 planes (hi, lo)
__device__ __align__(128) float g_sig[(size_t)K_ * N_];
__device__ __align__(128) float g_xn [(size_t)N_ * C_];
__device__ __align__(128) float g_xa [(size_t)N_ * C_];
__device__ __align__(128) float g_asum[N_];
__device__ __align__(128) float g_stats[7 * 2048];
__device__ int g_is64;
__device__ __align__(128) __nv_bfloat16 g_ahi[(size_t)N_ * C4_];
__device__ __align__(128) __nv_bfloat16 g_alo[(size_t)N_ * C4_];
#define WOFF_PPM1  0
#define WOFF_F1W0  65536
#define WOFF_F1W1  131072
#define WOFF_DIS1  196608
#define WOFF_DIS2  262144      /* 384x256 */
#define WOFF_F2W1  360448      /* 256x1024 */
#define WTOTAL     622592
__device__ __align__(128) __nv_bfloat16 g_whi[WTOTAL];
__device__ __align__(128) __nv_bfloat16 g_wlo[WTOTAL];

__device__ __forceinline__ float leaky(float x) { return x >= 0.f ? x : 0.01f * x; }

// ======================= utility kernels =======================
__global__ void k_zero(float* __restrict__ p, int n) {
    int i = blockIdx.x * blockDim.x + threadIdx.x;
    int stride = gridDim.x * blockDim.x;
    for (; i < n; i += stride) p[i] = 0.f;
}
__global__ void k_zero4(float4* __restrict__ p, int n4) {
    int i = blockIdx.x * blockDim.x + threadIdx.x;
    int stride = gridDim.x * blockDim.x;
    float4 z = make_float4(0.f, 0.f, 0.f, 0.f);
    for (; i < n4; i += stride) p[i] = z;
}
__global__ void k_nm2cm(const float* __restrict__ in, float* __restrict__ out) {
    __shared__ float tile[32][33];
    int nb = blockIdx.x * 32, cb = blockIdx.y * 32;
    int tx = threadIdx.x, ty = threadIdx.y;
#pragma unroll
    for (int i = 0; i < 32; i += 8)
        tile[ty + i][tx] = in[(size_t)(nb + ty + i) * C_ + cb + tx];
    __syncthreads();
#pragma unroll
    for (int i = 0; i < 32; i += 8)
        out[(size_t)(cb + ty + i) * N_ + nb + tx] = tile[tx][ty + i];
}

// ======================= BN stats (float4 loads) ==============
__global__ void k_stats(const float* __restrict__ x, float* __restrict__ st) {
    int c = blockIdx.x;
    const float4* xc = reinterpret_cast<const float4*>(x + (size_t)c * N_);
    int tid = threadIdx.x;
    float s = 0.f, s2 = 0.f;
    for (int i = blockIdx.y * 256 + tid; i < N_ / 4; i += 256 * gridDim.y) {
        float4 v = xc[i];
        s  += v.x + v.y + v.z + v.w;
        s2 += v.x * v.x + v.y * v.y + v.z * v.z + v.w * v.w;
    }
    __shared__ float sh[512];
    sh[tid] = s; sh[256 + tid] = s2;
    __syncthreads();
    for (int o = 128; o > 0; o >>= 1) {
        if (tid < o) { sh[tid] += sh[tid + o]; sh[256 + tid] += sh[256 + tid + o]; }
        __syncthreads();
    }
    if (tid == 0) {
        atomicAdd(&st[2 * c], sh[0]);
        atomicAdd(&st[2 * c + 1], sh[256]);
    }
}

// ======================= split/transpose conversion =======================
__global__ void k_split(const float* __restrict__ x, const float* __restrict__ gm,
                        const float* __restrict__ bt, const float* __restrict__ st,
                        __nv_bfloat16* __restrict__ hi, __nv_bfloat16* __restrict__ lo,
                        float* __restrict__ xout, int Kc, int flags) {
    __shared__ float tile[64][33];
    int nb = blockIdx.x * 32, kb = blockIdx.y * 64;
    int tx = threadIdx.x, ty = threadIdx.y;
    bool do_lk = flags & 1, do_bn = flags & 2;
#pragma unroll
    for (int i = 0; i < 64; i += 8) {
        int k = kb + ty + i;
        float v = x[(size_t)k * N_ + nb + tx];
        if (do_bn) {
            float m  = st[2 * k] * (1.f / N_);
            float vr = st[2 * k + 1] * (1.f / N_) - m * m;
            float rs = rsqrtf(vr + 1e-5f);
            float sc = rs * gm[k];
            v = v * sc + bt[k] - m * sc;
        }
        if (do_lk) v = leaky(v);
        tile[ty + i][tx] = v;
    }
    __syncthreads();
#pragma unroll
    for (int i = 0; i < 32; i += 8) {
        int n = nb + ty + i;
        float v0 = tile[2 * tx][ty + i];
        float v1 = tile[2 * tx + 1][ty + i];
        __nv_bfloat16 h0 = __float2bfloat16(v0);
        __nv_bfloat16 h1 = __float2bfloat16(v1);
        __nv_bfloat16 l0 = __float2bfloat16(v0 - __bfloat162float(h0));
        __nv_bfloat16 l1 = __float2bfloat16(v1 - __bfloat162float(h1));
        size_t base = (size_t)n * Kc + kb;
        reinterpret_cast<__nv_bfloat162*>(hi + base)[tx] = __nv_bfloat162(h0, h1);
        reinterpret_cast<__nv_bfloat162*>(lo + base)[tx] = __nv_bfloat162(l0, l1);
        if (xout) reinterpret_cast<float2*>(xout + base)[tx] = make_float2(v0, v1);
    }
}

// variant reading bf16 hi/lo channel-major input (dw3 path), always bn+leaky. Kc=1024.
__global__ void k_split_b(const __nv_bfloat16* __restrict__ xh, const __nv_bfloat16* __restrict__ xl,
                          const float* __restrict__ gm, const float* __restrict__ bt,
                          const float* __restrict__ st, __nv_bfloat16* __restrict__ hi,
                          __nv_bfloat16* __restrict__ lo) {
    __shared__ float tile[64][33];
    int nb = blockIdx.x * 32, kb = blockIdx.y * 64;
    int tx = threadIdx.x, ty = threadIdx.y;
#pragma unroll
    for (int i = 0; i < 64; i += 8) {
        int k = kb + ty + i;
        size_t idx = (size_t)k * N_ + nb + tx;
        float v = __bfloat162float(xh[idx]) + __bfloat162float(xl[idx]);
        float m  = st[2 * k] * (1.f / N_);
        float vr = st[2 * k + 1] * (1.f / N_) - m * m;
        float rs = rsqrtf(vr + 1e-5f);
        float sc = rs * gm[k];
        v = leaky(v * sc + bt[k] - m * sc);
        tile[ty + i][tx] = v;
    }
    __syncthreads();
#pragma unroll
    for (int i = 0; i < 32; i += 8) {
        int n = nb + ty + i;
        float v0 = tile[2 * tx][ty + i];
        float v1 = tile[2 * tx + 1][ty + i];
        __nv_bfloat16 h0 = __float2bfloat16(v0);
        __nv_bfloat16 h1 = __float2bfloat16(v1);
        __nv_bfloat16 l0 = __float2bfloat16(v0 - __bfloat162float(h0));
        __nv_bfloat16 l1 = __float2bfloat16(v1 - __bfloat162float(h1));
        size_t base = (size_t)n * C4_ + kb;
        reinterpret_cast<__nv_bfloat162*>(hi + base)[tx] = __nv_bfloat162(h0, h1);
        reinterpret_cast<__nv_bfloat162*>(lo + base)[tx] = __nv_bfloat162(l0, l1);
    }
}

// img += bn(t), then split(img or leaky(img)) into hi/lo (+xout). Kc=256.
__global__ void k_bnadd_split(const float* __restrict__ t, float* __restrict__ img,
                              const float* __restrict__ gm, const float* __restrict__ bt,
                              const float* __restrict__ st, __nv_bfloat16* __restrict__ hi,
                              __nv_bfloat16* __restrict__ lo, float* __restrict__ xout,
                              int do_lk) {
    __shared__ float tile[64][33];
    int nb = blockIdx.x * 32, kb = blockIdx.y * 64;
    int tx = threadIdx.x, ty = threadIdx.y;
#pragma unroll
    for (int i = 0; i < 64; i += 8) {
        int k = kb + ty + i;
        float m  = st[2 * k] * (1.f / N_);
        float vr = st[2 * k + 1] * (1.f / N_) - m * m;
        float rs = rsqrtf(vr + 1e-5f);
        float sc = rs * gm[k];
        float sb = bt[k] - m * sc;
        size_t idx = (size_t)k * N_ + nb + tx;
        float v = img[idx] + t[idx] * sc + sb;
        img[idx] = v;
        tile[ty + i][tx] = do_lk ? leaky(v) : v;
    }
    __syncthreads();
#pragma unroll
    for (int i = 0; i < 32; i += 8) {
        int n = nb + ty + i;
        float v0 = tile[2 * tx][ty + i];
        float v1 = tile[2 * tx + 1][ty + i];
        __nv_bfloat16 h0 = __float2bfloat16(v0);
        __nv_bfloat16 h1 = __float2bfloat16(v1);
        __nv_bfloat16 l0 = __float2bfloat16(v0 - __bfloat162float(h0));
        __nv_bfloat16 l1 = __float2bfloat16(v1 - __bfloat162float(h1));
        size_t base = (size_t)n * C_ + kb;
        reinterpret_cast<__nv_bfloat162*>(hi + base)[tx] = __nv_bfloat162(h0, h1);
        reinterpret_cast<__nv_bfloat162*>(lo + base)[tx] = __nv_bfloat162(l0, l1);
        if (xout) reinterpret_cast<float2*>(xout + base)[tx] = make_float2(v0, v1);
    }
}

// single-launch weight split for all 6 regions (blockIdx.y = region)
__global__ void k_wsplit6(const float* __restrict__ w0, const float* __restrict__ w1,
                          const float* __restrict__ w2, const float* __restrict__ w3,
                          const float* __restrict__ w4, const float* __restrict__ w5) {
    const int offs[6]  = {WOFF_PPM1, WOFF_F1W0, WOFF_F1W1, WOFF_DIS1, WOFF_DIS2, WOFF_F2W1};
    const int Ms[6]    = {256, 256, 256, 256, 289, 256};
    const int Mpads[6] = {256, 256, 256, 256, 384, 256};
    const int Kcs[6]   = {256, 256, 256, 256, 256, 1024};
    int rgn = blockIdx.y;
    const float* w = rgn == 0 ? w0 : rgn == 1 ? w1 : rgn == 2 ? w2 : rgn == 3 ? w3 : rgn == 4 ? w4 : w5;
    int off = offs[rgn], M = Ms[rgn], Kc = Kcs[rgn];
    int total = Mpads[rgn] * Kc;
    for (int i = blockIdx.x * blockDim.x + threadIdx.x; i < total; i += gridDim.x * blockDim.x) {
        int r = i / Kc;
        float v = (r < M) ? w[i] : 0.f;
        __nv_bfloat16 h = __float2bfloat16(v);
        g_whi[off + i] = h;
        g_wlo[off + i] = __float2bfloat16(v - __bfloat162float(h));
    }
}

// ======================= mma.sync bf16 GEMM (fp32 via hi/lo split) ============
// __launch_bounds__(256,2): probe-verified — regs clamp to 128, +11% per-CTA,
// but enables 2 CTAs/SM so the 288-CTA launches run in ONE wave instead of two.
// NOTE: keep this the ONLY GEMM instantiation in the binary (R5/R11 evidence).
#define GS_STAGE 32768
#define G_SMEM_TOTAL (3 * GS_STAGE + 1024)
__global__ __launch_bounds__(256, 2)
void k_gemm_mma(const __nv_bfloat16* __restrict__ Whi, const __nv_bfloat16* __restrict__ Wlo,
                const __nv_bfloat16* __restrict__ Ahi, const __nv_bfloat16* __restrict__ Alo,
                const float* __restrict__ bias, float* __restrict__ Y,
                int M, int Kc, int BIAS, int OUTLK) {
    extern __shared__ char smem_raw[];
    uint32_t sb = (smem_to_u32(smem_raw) + 1023u) & ~1023u;
    __shared__ float sbias[128];

    const int tid = threadIdx.x;
    const int w = tid >> 5, L = tid & 31;
    const int n0 = blockIdx.x * 128;
    const int m0 = blockIdx.y * 128;
    const int m_off = (w & 1) * 64;
    const int n_off = (w >> 1) * 32;

    if (BIAS && tid < 128) sbias[tid] = bias[m0 + tid];

    uint32_t aAddr, bAddr[4];
    {
        int r = m_off + (L & 15);
        uint32_t o = (uint32_t)((r >> 1) * 128 + (r & 1) * 64 + (L >> 4) * 16);
        aAddr = SWZ(o);
    }
#pragma unroll
    for (int nt = 0; nt < 4; nt++) {
        int r = n_off + nt * 8 + (L & 7);
        uint32_t o = (uint32_t)((r >> 1) * 128 + (r & 1) * 64 + ((L >> 3) & 1) * 16);
        bAddr[nt] = SWZ(o);
    }

    float acc[4][4][4];
#pragma unroll
    for (int i = 0; i < 4; i++)
#pragma unroll
        for (int j = 0; j < 4; j++)
#pragma unroll
            for (int q = 0; q < 4; q++) acc[i][j][q] = 0.f;

    const int nk = Kc >> 5;
    auto ldstage = [&](int t, int s) {
        uint32_t base = sb + s * GS_STAGE;
        int kc = t << 5;
#pragma unroll
        for (int i = 0; i < 2; i++) {
            int idx = tid + i * 256;
            int r = idx >> 2, c8 = idx & 3;
            uint32_t doff = SWZ((uint32_t)((r >> 1) * 128 + (r & 1) * 64 + c8 * 16));
            size_t goW = (size_t)(m0 + r) * Kc + kc + c8 * 8;
            size_t goA = (size_t)(n0 + r) * Kc + kc + c8 * 8;
            cpa16(base + doff,          Whi + goW);
            cpa16(base + 8192 + doff,   Wlo + goW);
            cpa16(base + 16384 + doff,  Ahi + goA);
            cpa16(base + 24576 + doff,  Alo + goA);
        }
        cpa_commit();
    };

    ldstage(0, 0);
    ldstage(1, 1);
    for (int t = 0; t < nk; t++) {
        cpa_wait<1>();
        __syncthreads();
        if (t + 2 < nk) ldstage(t + 2, (t + 2) % 3);
        else cpa_commit();
        uint32_t stW = sb + (t % 3) * GS_STAGE;
        uint32_t stA = stW + 16384;
#pragma unroll
        for (int kk = 0; kk < 2; kk++) {
            uint32_t kx = kk ? 0x20u : 0u;
            uint32_t bh[4][2], bl[4][2];
#pragma unroll
            for (int nt = 0; nt < 4; nt++) {
                ldm_x2(bh[nt], (stA + bAddr[nt]) ^ kx);
                ldm_x2(bl[nt], (stA + 8192 + bAddr[nt]) ^ kx);
            }
#pragma unroll
            for (int mt = 0; mt < 4; mt++) {
                uint32_t ah[4], al[4];
                ldm_x4(ah, (stW + aAddr + mt * 1024) ^ kx);
                ldm_x4(al, (stW + 8192 + aAddr + mt * 1024) ^ kx);
#pragma unroll
                for (int nt = 0; nt < 4; nt++) {
                    mma_bf16(acc[mt][nt], ah, bh[nt]);
                    mma_bf16(acc[mt][nt], ah, bl[nt]);
                    mma_bf16(acc[mt][nt], al, bh[nt]);
                }
            }
        }
    }

#pragma unroll
    for (int mt = 0; mt < 4; mt++) {
#pragma unroll
        for (int nt = 0; nt < 4; nt++) {
            int ocA = m0 + m_off + mt * 16 + (L >> 2);
            int n   = n0 + n_off + nt * 8 + 2 * (L & 3);
            float* d = acc[mt][nt];
            if (ocA < M) {
                float b0 = BIAS ? sbias[ocA - m0] : 0.f;
                float v0 = d[0] + b0, v1 = d[1] + b0;
                if (OUTLK) { v0 = leaky(v0); v1 = leaky(v1); }
                *reinterpret_cast<float2*>(Y + (size_t)ocA * N_ + n) = make_float2(v0, v1);
            }
            int ocB = ocA + 8;
            if (ocB < M) {
                float b1 = BIAS ? sbias[ocB - m0] : 0.f;
                float v2 = d[2] + b1, v3 = d[3] + b1;
                if (OUTLK) { v2 = leaky(v2); v3 = leaky(v3); }
                *reinterpret_cast<float2*>(Y + (size_t)ocB * N_ + n) = make_float2(v2, v3);
            }
        }
    }
}

// ======================= depthwise 17x17 (16-wide, two-phase register window) =
// Phase A: acc[0..7] with row[0..23]; Phase B: acc[8..15] with row[8..31].
// Peak live data regs ~40 (vs 48+ monolithic) so ptxas keeps the window in
// registers instead of re-loading from smem (R15 ncu: L1=73.8%, regs=48).
__global__ __launch_bounds__(256) void k_dw17(const float* __restrict__ L,
                                              const float* __restrict__ w0,
                                              float* __restrict__ out,
                                              float* __restrict__ st) {
    __shared__ float tile[80 * 84];
    __shared__ float ws[289];
    __shared__ float rs[8], rq[8];
    int c = blockIdx.y;
    int tb = blockIdx.x;
    int ty0 = (tb / 3) * 64, tx0 = (tb % 3) * 64;
    int tid = threadIdx.x;
    const float* Lc = L + (size_t)c * N_;
    for (int idx = tid; idx < 80 * 80; idx += 256) {
        int r = idx / 80, col = idx - r * 80;
        int gy = ty0 - 8 + r, gx = tx0 - 8 + col;
        float v = 0.f;
        if ((unsigned)gy < (unsigned)H_ && (unsigned)gx < (unsigned)W_) v = leaky(Lc[gy * W_ + gx]);
        tile[r * 84 + col] = v;
    }
    for (int idx = tid; idx < 289; idx += 256) ws[idx] = w0[c * 289 + idx];
    __syncthreads();

    int oy = tid >> 2;
    int ox = (tid & 3) * 16;
    float acc[16];
#pragma unroll
    for (int j = 0; j < 16; j++) acc[j] = 0.f;
    for (int ky = 0; ky < 17; ky++) {
        const float4* trow4 = reinterpret_cast<const float4*>(&tile[(oy + ky) * 84 + ox]);
        const float* wr = &ws[ky * 17];
        float row[32];
        // phase A: outputs 0..7, needs row[0..23]
#pragma unroll
        for (int i = 0; i < 6; i++) {
            float4 v = trow4[i];
            row[4 * i] = v.x; row[4 * i + 1] = v.y; row[4 * i + 2] = v.z; row[4 * i + 3] = v.w;
        }
#pragma unroll
        for (int kx = 0; kx < 17; kx++) {
            float w = wr[kx];
#pragma unroll
            for (int j = 0; j < 8; j++) acc[j] += w * row[kx + j];
        }
        // phase B: outputs 8..15, needs row[8..31]; row[0..7] now dead
#pragma unroll
        for (int i = 6; i < 8; i++) {
            float4 v = trow4[i];
            row[4 * i] = v.x; row[4 * i + 1] = v.y; row[4 * i + 2] = v.z; row[4 * i + 3] = v.w;
        }
#pragma unroll
        for (int kx = 0; kx < 17; kx++) {
            float w = wr[kx];
#pragma unroll
            for (int j = 8; j < 16; j++) acc[j] += w * row[kx + j];
        }
    }
    float* op = out + (size_t)c * N_ + (ty0 + oy) * W_ + tx0 + ox;
#pragma unroll
    for (int j = 0; j < 4; j++)
        *reinterpret_cast<float4*>(op + 4 * j) =
            make_float4(acc[4 * j], acc[4 * j + 1], acc[4 * j + 2], acc[4 * j + 3]);

    float s = 0.f, q = 0.f;
#pragma unroll
    for (int j = 0; j < 16; j++) { s += acc[j]; q += acc[j] * acc[j]; }
#pragma unroll
    for (int off = 16; off > 0; off >>= 1) {
        s += __shfl_xor_sync(0xffffffffu, s, off);
        q += __shfl_xor_sync(0xffffffffu, q, off);
    }
    if ((tid & 31) == 0) { rs[tid >> 5] = s; rq[tid >> 5] = q; }
    __syncthreads();
    if (tid == 0) {
        float S = 0.f, Q = 0.f;
#pragma unroll
        for (int i = 0; i < 8; i++) { S += rs[i]; Q += rq[i]; }
        atomicAdd(&st[2 * c], S);
        atomicAdd(&st[2 * c + 1], Q);
    }
}

// ======================= depthwise 3x3 x4 (bf16 hi/lo out + stats fused) ======
__global__ __launch_bounds__(256) void k_dw3(const float* __restrict__ L,
                                             const float* __restrict__ w,
                                             __nv_bfloat16* __restrict__ oh,
                                             __nv_bfloat16* __restrict__ ol,
                                             float* __restrict__ st) {
    __shared__ float tile[34 * 35];
    __shared__ float ws[36];
    int c = blockIdx.y;
    int tb = blockIdx.x;
    int ty0 = (tb / 6) * 32, tx0 = (tb % 6) * 32;
    int tid = threadIdx.x;
    const float* Lc = L + (size_t)c * N_;
    for (int idx = tid; idx < 34 * 34; idx += 256) {
        int r = idx / 34, col = idx - r * 34;
        int gy = ty0 - 1 + r, gx = tx0 - 1 + col;
        float v = 0.f;
        if ((unsigned)gy < (unsigned)H_ && (unsigned)gx < (unsigned)W_) v = leaky(Lc[gy * W_ + gx]);
        tile[r * 35 + col] = v;
    }
    if (tid < 36) ws[tid] = w[c * 36 + tid];
    __syncthreads();

    int oy = tid >> 3;
    int ox = (tid & 7) * 4;
    float acc[4][4];
#pragma unroll
    for (int j = 0; j < 4; j++)
#pragma unroll
        for (int q = 0; q < 4; q++) acc[j][q] = 0.f;
    for (int ky = 0; ky < 3; ky++) {
        const float* trow = &tile[(oy + ky) * 35 + ox];
        float row[6];
#pragma unroll
        for (int i = 0; i < 6; i++) row[i] = trow[i];
#pragma unroll
        for (int kx = 0; kx < 3; kx++) {
#pragma unroll
            for (int j = 0; j < 4; j++) {
                float wv = ws[j * 9 + ky * 3 + kx];
                acc[j][0] += wv * row[kx];
                acc[j][1] += wv * row[kx + 1];
                acc[j][2] += wv * row[kx + 2];
                acc[j][3] += wv * row[kx + 3];
            }
        }
    }
    int p = (ty0 + oy) * W_ + tx0 + ox;
#pragma unroll
    for (int j = 0; j < 4; j++) {
        size_t base = (size_t)(c * 4 + j) * N_ + p;
        __nv_bfloat16 h0 = __float2bfloat16(acc[j][0]);
        __nv_bfloat16 h1 = __float2bfloat16(acc[j][1]);
        __nv_bfloat16 h2 = __float2bfloat16(acc[j][2]);
        __nv_bfloat16 h3 = __float2bfloat16(acc[j][3]);
        reinterpret_cast<__nv_bfloat162*>(oh + base)[0] = __nv_bfloat162(h0, h1);
        reinterpret_cast<__nv_bfloat162*>(oh + base)[1] = __nv_bfloat162(h2, h3);
        __nv_bfloat16 l0 = __float2bfloat16(acc[j][0] - __bfloat162float(h0));
        __nv_bfloat16 l1 = __float2bfloat16(acc[j][1] - __bfloat162float(h1));
        __nv_bfloat16 l2 = __float2bfloat16(acc[j][2] - __bfloat162float(h2));
        __nv_bfloat16 l3 = __float2bfloat16(acc[j][3] - __bfloat162float(h3));
        reinterpret_cast<__nv_bfloat162*>(ol + base)[0] = __nv_bfloat162(l0, l1);
        reinterpret_cast<__nv_bfloat162*>(ol + base)[1] = __nv_bfloat162(l2, l3);
    }
#pragma unroll
    for (int j = 0; j < 4; j++) {
        float s = acc[j][0] + acc[j][1] + acc[j][2] + acc[j][3];
        float q = acc[j][0] * acc[j][0] + acc[j][1] * acc[j][1]
                + acc[j][2] * acc[j][2] + acc[j][3] * acc[j][3];
#pragma unroll
        for (int off = 16; off > 0; off >>= 1) {
            s += __shfl_xor_sync(0xffffffffu, s, off);
            q += __shfl_xor_sync(0xffffffffu, q, off);
        }
        if ((tid & 31) == 0) {
            atomicAdd(&st[2 * (c * 4 + j)], s);
            atomicAdd(&st[2 * (c * 4 + j) + 1], q);
        }
    }
}

// ======================= edge stage (fused) =======================
__global__ void k_detect(const int* __restrict__ info32) {
    if (blockIdx.x == 0 && threadIdx.x == 0) {
        long long s = 0;
        for (int i = 1; i < 256; i += 2) {
            int v = info32[i];
            s += (v < 0) ? -(long long)v : (long long)v;
        }
        g_is64 = (s == 0) ? 1 : 0;
    }
}
__device__ __forceinline__ void load_edge(const void* info, int e, int& src, int& k1, int& dst, int& k2) {
    if (g_is64) {
        const long long* q = reinterpret_cast<const long long*>(info) + (size_t)e * 4;
        src = (int)q[0]; k1 = (int)q[1]; dst = (int)q[2]; k2 = (int)q[3];
    } else {
        const int* q = reinterpret_cast<const int*>(info) + (size_t)e * 4;
        src = q[0]; k1 = q[1]; dst = q[2]; k2 = q[3];
    }
}
__global__ void k_edge(const void* __restrict__ info, const float* __restrict__ msk) {
    int w = (blockIdx.x * blockDim.x + threadIdx.x) >> 5;
    int lane = threadIdx.x & 31;
    if (w >= E_) return;
    int src = 0, dst = 0;
    float a = 0.f;
    if (lane == 0) {
        int k1, k2;
        load_edge(info, w, src, k1, dst, k2);
        float mk = msk[w];
        if (mk != 0.f) {
            float s = g_sig[(size_t)k1 * N_ + src] + g_sig[(size_t)k2 * N_ + dst];
            s = fminf(fmaxf(s, -5.f), 5.f);
            a = expf(s) * mk;
        }
        if (a != 0.f) atomicAdd(&g_asum[dst], a);
    }
    a = __shfl_sync(0xffffffffu, a, 0);
    if (a == 0.f) return;
    src = __shfl_sync(0xffffffffu, src, 0);
    dst = __shfl_sync(0xffffffffu, dst, 0);
    const float4* xs = reinterpret_cast<const float4*>(g_xn + (size_t)src * C_);
    float* xd = g_xa + (size_t)dst * C_;
#pragma unroll
    for (int i = 0; i < 2; i++) {
        int c4 = lane + 32 * i;
        float4 v = xs[c4];
        red_v4(xd + c4 * 4, v.x * a, v.y * a, v.z * a, v.w * a);
    }
}
__global__ void k_xtrans_stats(float* __restrict__ st) {
    int c = blockIdx.x * 32 + threadIdx.x;
    int ty = threadIdx.y;
    float s = 0.f, s2 = 0.f;
    for (int n = blockIdx.y * 8 + ty; n < N_; n += gridDim.y * 8) {
        float d = g_asum[n] + 1e-5f;
        size_t idx = (size_t)n * C_ + c;
        float v = g_xa[idx] / d;
        g_xa[idx] = v;
        s += v; s2 += v * v;
    }
    __shared__ float sh[8][32], sh2[8][32];
    sh[ty][threadIdx.x] = s; sh2[ty][threadIdx.x] = s2;
    __syncthreads();
    if (ty == 0) {
#pragma unroll
        for (int i = 1; i < 8; i++) { s += sh[i][threadIdx.x]; s2 += sh2[i][threadIdx.x]; }
        atomicAdd(&st[2 * c], s);
        atomicAdd(&st[2 * c + 1], s2);
    }
}
__global__ void k_bn1d_add(const float* __restrict__ gm, const float* __restrict__ bt,
                           const float* __restrict__ st) {
    __shared__ float tile[32][33];
    int nb = blockIdx.x * 32, cb = blockIdx.y * 32;
    int tx = threadIdx.x, ty = threadIdx.y;
#pragma unroll
    for (int i = 0; i < 32; i += 8)
        tile[ty + i][tx] = g_xa[(size_t)(nb + ty + i) * C_ + cb + tx];
    __syncthreads();
#pragma unroll
    for (int i = 0; i < 32; i += 8) {
        int c = cb + ty + i;
        float m  = st[2 * c] * (1.f / N_);
        float vr = st[2 * c + 1] * (1.f / N_) - m * m;
        float rs = rsqrtf(vr + 1e-5f);
        float sc = rs * gm[c];
        float sb = bt[c] - m * sc;
        g_img[(size_t)c * N_ + nb + tx] += tile[tx][ty + i] * sc + sb;
    }
}
__global__ void k_final(const float* __restrict__ gm, const float* __restrict__ bt,
                        const float* __restrict__ st, float* __restrict__ out) {
    __shared__ float tile[32][33];
    int nb = blockIdx.x * 32, cb = blockIdx.y * 32;
    int tx = threadIdx.x, ty = threadIdx.y;
#pragma unroll
    for (int i = 0; i < 32; i += 8) {
        int c = cb + ty + i;
        float m  = st[2 * c] * (1.f / N_);
        float vr = st[2 * c + 1] * (1.f / N_) - m * m;
        float rs = rsqrtf(vr + 1e-5f);
        float sc = rs * gm[c];
        float sb = bt[c] - m * sc;
        size_t idx = (size_t)c * N_ + nb + tx;
        tile[ty + i][tx] = g_t2[idx] * sc + sb + g_img[idx];
    }
    __syncthreads();
#pragma unroll
    for (int i = 0; i < 32; i += 8)
        out[(size_t)(nb + ty + i) * C_ + cb + tx] = tile[tx][ty + i];
}

// ======================= host orchestration =======================
extern "C" void kernel_launch(void* const* d_in, const int* in_sizes, int n_in,
                              void* d_out, int out_size) {
    const float* X       = (const float*)d_in[0];
    const void*  info    = d_in[1];
    const float* msk     = (const float*)d_in[2];
    const float* ppm_w0  = (const float*)d_in[3];
    const float* ppm_g0  = (const float*)d_in[4];
    const float* ppm_b0  = (const float*)d_in[5];
    const float* ppm_w1  = (const float*)d_in[6];
    const float* ppm_g1  = (const float*)d_in[7];
    const float* ppm_b1  = (const float*)d_in[8];
    const float* ffn1_w0 = (const float*)d_in[9];
    const float* ffn1_g0 = (const float*)d_in[10];
    const float* ffn1_b0 = (const float*)d_in[11];
    const float* ffn1_w1 = (const float*)d_in[12];
    const float* ffn1_g1 = (const float*)d_in[13];
    const float* ffn1_b1 = (const float*)d_in[14];
    const float* dis_w1  = (const float*)d_in[15];
    const float* dis_b1  = (const float*)d_in[16];
    const float* dis_w2  = (const float*)d_in[17];
    const float* dis_b2  = (const float*)d_in[18];
    const float* bn_g    = (const float*)d_in[19];
    const float* bn_b    = (const float*)d_in[20];
    const float* ffn2_w0 = (const float*)d_in[21];
    const float* ffn2_g0 = (const float*)d_in[22];
    const float* ffn2_b0 = (const float*)d_in[23];
    const float* ffn2_w1 = (const float*)d_in[24];
    const float* ffn2_g1 = (const float*)d_in[25];
    const float* ffn2_b1 = (const float*)d_in[26];
    float* out = (float*)d_out;

    float *img, *tb, *t2, *big, *sig, *xn, *xa, *asum, *stats;
    __nv_bfloat16 *ahi, *alo, *whi, *wlo;
    cudaGetSymbolAddress((void**)&img,   g_img);
    cudaGetSymbolAddress((void**)&tb,    g_tb);
    cudaGetSymbolAddress((void**)&t2,    g_t2);
    cudaGetSymbolAddress((void**)&big,   g_big);
    cudaGetSymbolAddress((void**)&sig,   g_sig);
    cudaGetSymbolAddress((void**)&xn,    g_xn);
    cudaGetSymbolAddress((void**)&xa,    g_xa);
    cudaGetSymbolAddress((void**)&asum,  g_asum);
    cudaGetSymbolAddress((void**)&stats, g_stats);
    cudaGetSymbolAddress((void**)&ahi,   g_ahi);
    cudaGetSymbolAddress((void**)&alo,   g_alo);
    cudaGetSymbolAddress((void**)&whi,   g_whi);
    cudaGetSymbolAddress((void**)&wlo,   g_wlo);
    __nv_bfloat16* bigh = (__nv_bfloat16*)big;
    __nv_bfloat16* bigl = bigh + (size_t)C4_ * N_;

    static bool attr_done = false;
    if (!attr_done) {
        cudaFuncSetAttribute(k_gemm_mma, cudaFuncAttributeMaxDynamicSharedMemorySize, G_SMEM_TOTAL);
        attr_done = true;
    }

    float* st0 = stats + 0 * 2048;   // dw17 out
    float* st1 = stats + 1 * 2048;   // ppm1 gemm out
    float* st2 = stats + 2 * 2048;   // f1w0 gemm out
    float* st3 = stats + 3 * 2048;   // f1w1 gemm out
    float* st4 = stats + 4 * 2048;   // x_trans
    float* st5 = stats + 5 * 2048;   // dw3 out
    float* st6 = stats + 6 * 2048;   // f2w1 gemm out

    dim3 b32x8(32, 8);
    dim3 gT(N_ / 32, C_ / 32);
    dim3 gS(N_ / 32, 4);
    dim3 gStat(C_, 4);

    auto gemm = [&](int woff, const float* bias, float* Y,
                    int M, int Mpad, int Kc, int BIAS, int OUTLK) {
        k_gemm_mma<<<dim3(N_ / 128, Mpad / 128), 256, G_SMEM_TOTAL>>>(
            whi + woff, wlo + woff, ahi, alo, bias, Y, M, Kc, BIAS, OUTLK);
    };

    // launches 0-3: dw17 lands at ncu capture slot 3 (verify two-phase prediction)
    k_detect<<<1, 32>>>((const int*)info);
    k_zero<<<16, 256>>>(stats, 7 * 2048);
    k_nm2cm<<<gT, b32x8>>>(X, img);
    k_dw17<<<dim3(9, C_), 256>>>(img, ppm_w0, tb, st0);
    // remaining setup
    k_wsplit6<<<dim3(96, 6), 256>>>(ppm_w1, ffn1_w0, ffn1_w1, dis_w1, dis_w2, ffn2_w1);
    k_zero<<<36, 256>>>(asum, N_);
    k_zero4<<<(N_ * C_ / 4 + 255) / 256, 256>>>((float4*)xa, N_ * C_ / 4);

    // ---- PPM ----
    k_split<<<gS, b32x8>>>(tb, ppm_g0, ppm_b0, st0, ahi, alo, nullptr, C_, 3);
    gemm(WOFF_PPM1, nullptr, t2, 256, 256, 256, 0, 0);
    k_stats<<<gStat, 256>>>(t2, st1);
    k_bnadd_split<<<gS, b32x8>>>(t2, img, ppm_g1, ppm_b1, st1, ahi, alo, nullptr, 1);

    // ---- FFN1 ----
    gemm(WOFF_F1W0, nullptr, tb, 256, 256, 256, 0, 0);
    k_stats<<<gStat, 256>>>(tb, st2);
    k_split<<<gS, b32x8>>>(tb, ffn1_g0, ffn1_b0, st2, ahi, alo, nullptr, C_, 3);
    gemm(WOFF_F1W1, nullptr, t2, 256, 256, 256, 0, 0);
    k_stats<<<gStat, 256>>>(t2, st3);
    k_bnadd_split<<<gS, b32x8>>>(t2, img, ffn1_g1, ffn1_b1, st3, ahi, alo, xn, 0);

    // ---- discriminator / graph attention ----
    gemm(WOFF_DIS1, dis_b1, tb, 256, 256, 256, 1, 1);
    k_split<<<gS, b32x8>>>(tb, nullptr, nullptr, nullptr, ahi, alo, nullptr, C_, 0);
    gemm(WOFF_DIS2, dis_b2, sig, 289, 384, 256, 1, 0);
    k_edge<<<E_ / 8, 256>>>(info, msk);
    k_xtrans_stats<<<dim3(8, 64), b32x8>>>(st4);
    k_bn1d_add<<<gT, b32x8>>>(bn_g, bn_b, st4);

    // ---- FFN2 ----
    k_dw3<<<dim3(36, C_), 256>>>(img, ffn2_w0, bigh, bigl, st5);
    k_split_b<<<dim3(N_ / 32, C4_ / 64), b32x8>>>(bigh, bigl, ffn2_g0, ffn2_b0, st5, ahi, alo);
    gemm(WOFF_F2W1, nullptr, t2, 256, 256, 1024, 0, 0);
    k_stats<<<gStat, 256>>>(t2, st6);
    k_final<<<gT, b32x8>>>(ffn2_g1, ffn2_b1, st6, out);

    (void)in_sizes; (void)n_in; (void)out_size;
}

// round 17
// speedup vs baseline: 1.4020x; 1.4020x over previous
#include <cuda_runtime.h>
#include <cuda_bf16.h>
#include <cstdint>
#include <math.h>

#define H_ 192
#define W_ 192
#define C_ 256
#define C4_ 1024
#define N_ 36864
#define E_ 294912
#define K_ 289

// ======================= PTX helpers (base sm_103 target: NO tcgen05) ==========
__device__ __forceinline__ uint32_t smem_to_u32(const void* p) {
    uint32_t a;
    asm("{ .reg .u64 t; cvta.to.shared.u64 t, %1; cvt.u32.u64 %0, t; }" : "=r"(a) : "l"(p));
    return a;
}
__device__ __forceinline__ void cpa16(uint32_t dst, const void* src) {
    asm volatile("cp.async.cg.shared.global [%0], [%1], 16;" :: "r"(dst), "l"(src) : "memory");
}
__device__ __forceinline__ void cpa_commit() {
    asm volatile("cp.async.commit_group;" ::: "memory");
}
template<int NN>
__device__ __forceinline__ void cpa_wait() {
    asm volatile("cp.async.wait_group %0;" :: "n"(NN) : "memory");
}
__device__ __forceinline__ void ldm_x4(uint32_t* r, uint32_t addr) {
    asm volatile("ldmatrix.sync.aligned.m8n8.x4.shared.b16 {%0,%1,%2,%3}, [%4];"
        : "=r"(r[0]), "=r"(r[1]), "=r"(r[2]), "=r"(r[3]) : "r"(addr));
}
__device__ __forceinline__ void ldm_x2(uint32_t* r, uint32_t addr) {
    asm volatile("ldmatrix.sync.aligned.m8n8.x2.shared.b16 {%0,%1}, [%2];"
        : "=r"(r[0]), "=r"(r[1]) : "r"(addr));
}
__device__ __forceinline__ void mma_bf16(float* d, const uint32_t* a, const uint32_t* b) {
    asm volatile("mma.sync.aligned.m16n8k16.row.col.f32.bf16.bf16.f32 "
        "{%0,%1,%2,%3}, {%4,%5,%6,%7}, {%8,%9}, {%0,%1,%2,%3};"
        : "+f"(d[0]), "+f"(d[1]), "+f"(d[2]), "+f"(d[3])
        : "r"(a[0]), "r"(a[1]), "r"(a[2]), "r"(a[3]), "r"(b[0]), "r"(b[1]));
}
__device__ __forceinline__ void red_v4(float* p, float a, float b, float c, float d) {
    asm volatile("red.global.add.v4.f32 [%0], {%1,%2,%3,%4};"
        :: "l"(p), "f"(a), "f"(b), "f"(c), "f"(d) : "memory");
}
#define SWZ(o) ((o) ^ (((o) >> 3) & 0x70))

// ======================= scratch =======================
__device__ __align__(128) float g_img[(size_t)C_ * N_];
__device__ __align__(128) float g_tb [(size_t)C_ * N_];
__device__ __align__(128) float g_t2 [(size_t)C_ * N_];
__device__ __align__(128) float g_big[(size_t)C4_ * N_];   // dw3 out: 2x bf16 planes (hi, lo)
__device__ __align__(128) float g_sig[(size_t)K_ * N_];
__device__ __align__(128) float g_xn [(size_t)N_ * C_];
__device__ __align__(128) float g_xa [(size_t)N_ * C_];
__device__ __align__(128) float g_asum[N_];
__device__ __align__(128) float g_stats[7 * 2048];
__device__ int g_is64;
__device__ __align__(128) __nv_bfloat16 g_ahi[(size_t)N_ * C4_];
__device__ __align__(128) __nv_bfloat16 g_alo[(size_t)N_ * C4_];
#define WOFF_PPM1  0
#define WOFF_F1W0  65536
#define WOFF_F1W1  131072
#define WOFF_DIS1  196608
#define WOFF_DIS2  262144      /* 384x256 */
#define WOFF_F2W1  360448      /* 256x1024 */
#define WTOTAL     622592
__device__ __align__(128) __nv_bfloat16 g_whi[WTOTAL];
__device__ __align__(128) __nv_bfloat16 g_wlo[WTOTAL];

__device__ __forceinline__ float leaky(float x) { return x >= 0.f ? x : 0.01f * x; }

// ======================= utility kernels =======================
__global__ void k_zero(float* __restrict__ p, int n) {
    int i = blockIdx.x * blockDim.x + threadIdx.x;
    int stride = gridDim.x * blockDim.x;
    for (; i < n; i += stride) p[i] = 0.f;
}
__global__ void k_zero4(float4* __restrict__ p, int n4) {
    int i = blockIdx.x * blockDim.x + threadIdx.x;
    int stride = gridDim.x * blockDim.x;
    float4 z = make_float4(0.f, 0.f, 0.f, 0.f);
    for (; i < n4; i += stride) p[i] = z;
}
__global__ void k_nm2cm(const float* __restrict__ in, float* __restrict__ out) {
    __shared__ float tile[32][33];
    int nb = blockIdx.x * 32, cb = blockIdx.y * 32;
    int tx = threadIdx.x, ty = threadIdx.y;
#pragma unroll
    for (int i = 0; i < 32; i += 8)
        tile[ty + i][tx] = in[(size_t)(nb + ty + i) * C_ + cb + tx];
    __syncthreads();
#pragma unroll
    for (int i = 0; i < 32; i += 8)
        out[(size_t)(cb + ty + i) * N_ + nb + tx] = tile[tx][ty + i];
}

// ======================= BN stats (float4 loads) ==============
__global__ void k_stats(const float* __restrict__ x, float* __restrict__ st) {
    int c = blockIdx.x;
    const float4* xc = reinterpret_cast<const float4*>(x + (size_t)c * N_);
    int tid = threadIdx.x;
    float s = 0.f, s2 = 0.f;
    for (int i = blockIdx.y * 256 + tid; i < N_ / 4; i += 256 * gridDim.y) {
        float4 v = xc[i];
        s  += v.x + v.y + v.z + v.w;
        s2 += v.x * v.x + v.y * v.y + v.z * v.z + v.w * v.w;
    }
    __shared__ float sh[512];
    sh[tid] = s; sh[256 + tid] = s2;
    __syncthreads();
    for (int o = 128; o > 0; o >>= 1) {
        if (tid < o) { sh[tid] += sh[tid + o]; sh[256 + tid] += sh[256 + tid + o]; }
        __syncthreads();
    }
    if (tid == 0) {
        atomicAdd(&st[2 * c], sh[0]);
        atomicAdd(&st[2 * c + 1], sh[256]);
    }
}

// ======================= split/transpose conversion =======================
__global__ void k_split(const float* __restrict__ x, const float* __restrict__ gm,
                        const float* __restrict__ bt, const float* __restrict__ st,
                        __nv_bfloat16* __restrict__ hi, __nv_bfloat16* __restrict__ lo,
                        float* __restrict__ xout, int Kc, int flags) {
    __shared__ float tile[64][33];
    int nb = blockIdx.x * 32, kb = blockIdx.y * 64;
    int tx = threadIdx.x, ty = threadIdx.y;
    bool do_lk = flags & 1, do_bn = flags & 2;
#pragma unroll
    for (int i = 0; i < 64; i += 8) {
        int k = kb + ty + i;
        float v = x[(size_t)k * N_ + nb + tx];
        if (do_bn) {
            float m  = st[2 * k] * (1.f / N_);
            float vr = st[2 * k + 1] * (1.f / N_) - m * m;
            float rs = rsqrtf(vr + 1e-5f);
            float sc = rs * gm[k];
            v = v * sc + bt[k] - m * sc;
        }
        if (do_lk) v = leaky(v);
        tile[ty + i][tx] = v;
    }
    __syncthreads();
#pragma unroll
    for (int i = 0; i < 32; i += 8) {
        int n = nb + ty + i;
        float v0 = tile[2 * tx][ty + i];
        float v1 = tile[2 * tx + 1][ty + i];
        __nv_bfloat16 h0 = __float2bfloat16(v0);
        __nv_bfloat16 h1 = __float2bfloat16(v1);
        __nv_bfloat16 l0 = __float2bfloat16(v0 - __bfloat162float(h0));
        __nv_bfloat16 l1 = __float2bfloat16(v1 - __bfloat162float(h1));
        size_t base = (size_t)n * Kc + kb;
        reinterpret_cast<__nv_bfloat162*>(hi + base)[tx] = __nv_bfloat162(h0, h1);
        reinterpret_cast<__nv_bfloat162*>(lo + base)[tx] = __nv_bfloat162(l0, l1);
        if (xout) reinterpret_cast<float2*>(xout + base)[tx] = make_float2(v0, v1);
    }
}

// variant reading bf16 hi/lo channel-major input (dw3 path), always bn+leaky. Kc=1024.
__global__ void k_split_b(const __nv_bfloat16* __restrict__ xh, const __nv_bfloat16* __restrict__ xl,
                          const float* __restrict__ gm, const float* __restrict__ bt,
                          const float* __restrict__ st, __nv_bfloat16* __restrict__ hi,
                          __nv_bfloat16* __restrict__ lo) {
    __shared__ float tile[64][33];
    int nb = blockIdx.x * 32, kb = blockIdx.y * 64;
    int tx = threadIdx.x, ty = threadIdx.y;
#pragma unroll
    for (int i = 0; i < 64; i += 8) {
        int k = kb + ty + i;
        size_t idx = (size_t)k * N_ + nb + tx;
        float v = __bfloat162float(xh[idx]) + __bfloat162float(xl[idx]);
        float m  = st[2 * k] * (1.f / N_);
        float vr = st[2 * k + 1] * (1.f / N_) - m * m;
        float rs = rsqrtf(vr + 1e-5f);
        float sc = rs * gm[k];
        v = leaky(v * sc + bt[k] - m * sc);
        tile[ty + i][tx] = v;
    }
    __syncthreads();
#pragma unroll
    for (int i = 0; i < 32; i += 8) {
        int n = nb + ty + i;
        float v0 = tile[2 * tx][ty + i];
        float v1 = tile[2 * tx + 1][ty + i];
        __nv_bfloat16 h0 = __float2bfloat16(v0);
        __nv_bfloat16 h1 = __float2bfloat16(v1);
        __nv_bfloat16 l0 = __float2bfloat16(v0 - __bfloat162float(h0));
        __nv_bfloat16 l1 = __float2bfloat16(v1 - __bfloat162float(h1));
        size_t base = (size_t)n * C4_ + kb;
        reinterpret_cast<__nv_bfloat162*>(hi + base)[tx] = __nv_bfloat162(h0, h1);
        reinterpret_cast<__nv_bfloat162*>(lo + base)[tx] = __nv_bfloat162(l0, l1);
    }
}

// img += bn(t), then split(img or leaky(img)) into hi/lo (+xout). Kc=256.
__global__ void k_bnadd_split(const float* __restrict__ t, float* __restrict__ img,
                              const float* __restrict__ gm, const float* __restrict__ bt,
                              const float* __restrict__ st, __nv_bfloat16* __restrict__ hi,
                              __nv_bfloat16* __restrict__ lo, float* __restrict__ xout,
                              int do_lk) {
    __shared__ float tile[64][33];
    int nb = blockIdx.x * 32, kb = blockIdx.y * 64;
    int tx = threadIdx.x, ty = threadIdx.y;
#pragma unroll
    for (int i = 0; i < 64; i += 8) {
        int k = kb + ty + i;
        float m  = st[2 * k] * (1.f / N_);
        float vr = st[2 * k + 1] * (1.f / N_) - m * m;
        float rs = rsqrtf(vr + 1e-5f);
        float sc = rs * gm[k];
        float sb = bt[k] - m * sc;
        size_t idx = (size_t)k * N_ + nb + tx;
        float v = img[idx] + t[idx] * sc + sb;
        img[idx] = v;
        tile[ty + i][tx] = do_lk ? leaky(v) : v;
    }
    __syncthreads();
#pragma unroll
    for (int i = 0; i < 32; i += 8) {
        int n = nb + ty + i;
        float v0 = tile[2 * tx][ty + i];
        float v1 = tile[2 * tx + 1][ty + i];
        __nv_bfloat16 h0 = __float2bfloat16(v0);
        __nv_bfloat16 h1 = __float2bfloat16(v1);
        __nv_bfloat16 l0 = __float2bfloat16(v0 - __bfloat162float(h0));
        __nv_bfloat16 l1 = __float2bfloat16(v1 - __bfloat162float(h1));
        size_t base = (size_t)n * C_ + kb;
        reinterpret_cast<__nv_bfloat162*>(hi + base)[tx] = __nv_bfloat162(h0, h1);
        reinterpret_cast<__nv_bfloat162*>(lo + base)[tx] = __nv_bfloat162(l0, l1);
        if (xout) reinterpret_cast<float2*>(xout + base)[tx] = make_float2(v0, v1);
    }
}

// single-launch weight split for all 6 regions (blockIdx.y = region)
__global__ void k_wsplit6(const float* __restrict__ w0, const float* __restrict__ w1,
                          const float* __restrict__ w2, const float* __restrict__ w3,
                          const float* __restrict__ w4, const float* __restrict__ w5) {
    const int offs[6]  = {WOFF_PPM1, WOFF_F1W0, WOFF_F1W1, WOFF_DIS1, WOFF_DIS2, WOFF_F2W1};
    const int Ms[6]    = {256, 256, 256, 256, 289, 256};
    const int Mpads[6] = {256, 256, 256, 256, 384, 256};
    const int Kcs[6]   = {256, 256, 256, 256, 256, 1024};
    int rgn = blockIdx.y;
    const float* w = rgn == 0 ? w0 : rgn == 1 ? w1 : rgn == 2 ? w2 : rgn == 3 ? w3 : rgn == 4 ? w4 : w5;
    int off = offs[rgn], M = Ms[rgn], Kc = Kcs[rgn];
    int total = Mpads[rgn] * Kc;
    for (int i = blockIdx.x * blockDim.x + threadIdx.x; i < total; i += gridDim.x * blockDim.x) {
        int r = i / Kc;
        float v = (r < M) ? w[i] : 0.f;
        __nv_bfloat16 h = __float2bfloat16(v);
        g_whi[off + i] = h;
        g_wlo[off + i] = __float2bfloat16(v - __bfloat162float(h));
    }
}

// ======================= mma.sync bf16 GEMM (fp32 via hi/lo split) ============
// __launch_bounds__(256,2): probe-verified — regs clamp to 128, +11% per-CTA,
// but enables 2 CTAs/SM so the 288-CTA launches run in ONE wave instead of two.
// NOTE: keep this the ONLY GEMM instantiation in the binary (R5/R11 evidence).
#define GS_STAGE 32768
#define G_SMEM_TOTAL (3 * GS_STAGE + 1024)
__global__ __launch_bounds__(256, 2)
void k_gemm_mma(const __nv_bfloat16* __restrict__ Whi, const __nv_bfloat16* __restrict__ Wlo,
                const __nv_bfloat16* __restrict__ Ahi, const __nv_bfloat16* __restrict__ Alo,
                const float* __restrict__ bias, float* __restrict__ Y,
                int M, int Kc, int BIAS, int OUTLK) {
    extern __shared__ char smem_raw[];
    uint32_t sb = (smem_to_u32(smem_raw) + 1023u) & ~1023u;
    __shared__ float sbias[128];

    const int tid = threadIdx.x;
    const int w = tid >> 5, L = tid & 31;
    const int n0 = blockIdx.x * 128;
    const int m0 = blockIdx.y * 128;
    const int m_off = (w & 1) * 64;
    const int n_off = (w >> 1) * 32;

    if (BIAS && tid < 128) sbias[tid] = bias[m0 + tid];

    uint32_t aAddr, bAddr[4];
    {
        int r = m_off + (L & 15);
        uint32_t o = (uint32_t)((r >> 1) * 128 + (r & 1) * 64 + (L >> 4) * 16);
        aAddr = SWZ(o);
    }
#pragma unroll
    for (int nt = 0; nt < 4; nt++) {
        int r = n_off + nt * 8 + (L & 7);
        uint32_t o = (uint32_t)((r >> 1) * 128 + (r & 1) * 64 + ((L >> 3) & 1) * 16);
        bAddr[nt] = SWZ(o);
    }

    float acc[4][4][4];
#pragma unroll
    for (int i = 0; i < 4; i++)
#pragma unroll
        for (int j = 0; j < 4; j++)
#pragma unroll
            for (int q = 0; q < 4; q++) acc[i][j][q] = 0.f;

    const int nk = Kc >> 5;
    auto ldstage = [&](int t, int s) {
        uint32_t base = sb + s * GS_STAGE;
        int kc = t << 5;
#pragma unroll
        for (int i = 0; i < 2; i++) {
            int idx = tid + i * 256;
            int r = idx >> 2, c8 = idx & 3;
            uint32_t doff = SWZ((uint32_t)((r >> 1) * 128 + (r & 1) * 64 + c8 * 16));
            size_t goW = (size_t)(m0 + r) * Kc + kc + c8 * 8;
            size_t goA = (size_t)(n0 + r) * Kc + kc + c8 * 8;
            cpa16(base + doff,          Whi + goW);
            cpa16(base + 8192 + doff,   Wlo + goW);
            cpa16(base + 16384 + doff,  Ahi + goA);
            cpa16(base + 24576 + doff,  Alo + goA);
        }
        cpa_commit();
    };

    ldstage(0, 0);
    ldstage(1, 1);
    for (int t = 0; t < nk; t++) {
        cpa_wait<1>();
        __syncthreads();
        if (t + 2 < nk) ldstage(t + 2, (t + 2) % 3);
        else cpa_commit();
        uint32_t stW = sb + (t % 3) * GS_STAGE;
        uint32_t stA = stW + 16384;
#pragma unroll
        for (int kk = 0; kk < 2; kk++) {
            uint32_t kx = kk ? 0x20u : 0u;
            uint32_t bh[4][2], bl[4][2];
#pragma unroll
            for (int nt = 0; nt < 4; nt++) {
                ldm_x2(bh[nt], (stA + bAddr[nt]) ^ kx);
                ldm_x2(bl[nt], (stA + 8192 + bAddr[nt]) ^ kx);
            }
#pragma unroll
            for (int mt = 0; mt < 4; mt++) {
                uint32_t ah[4], al[4];
                ldm_x4(ah, (stW + aAddr + mt * 1024) ^ kx);
                ldm_x4(al, (stW + 8192 + aAddr + mt * 1024) ^ kx);
#pragma unroll
                for (int nt = 0; nt < 4; nt++) {
                    mma_bf16(acc[mt][nt], ah, bh[nt]);
                    mma_bf16(acc[mt][nt], ah, bl[nt]);
                    mma_bf16(acc[mt][nt], al, bh[nt]);
                }
            }
        }
    }

#pragma unroll
    for (int mt = 0; mt < 4; mt++) {
#pragma unroll
        for (int nt = 0; nt < 4; nt++) {
            int ocA = m0 + m_off + mt * 16 + (L >> 2);
            int n   = n0 + n_off + nt * 8 + 2 * (L & 3);
            float* d = acc[mt][nt];
            if (ocA < M) {
                float b0 = BIAS ? sbias[ocA - m0] : 0.f;
                float v0 = d[0] + b0, v1 = d[1] + b0;
                if (OUTLK) { v0 = leaky(v0); v1 = leaky(v1); }
                *reinterpret_cast<float2*>(Y + (size_t)ocA * N_ + n) = make_float2(v0, v1);
            }
            int ocB = ocA + 8;
            if (ocB < M) {
                float b1 = BIAS ? sbias[ocB - m0] : 0.f;
                float v2 = d[2] + b1, v3 = d[3] + b1;
                if (OUTLK) { v2 = leaky(v2); v3 = leaky(v3); }
                *reinterpret_cast<float2*>(Y + (size_t)ocB * N_ + n) = make_float2(v2, v3);
            }
        }
    }
}

// ======================= depthwise 17x17 (16-wide, stride-84 LDS.128) =========
__global__ __launch_bounds__(256) void k_dw17(const float* __restrict__ L,
                                              const float* __restrict__ w0,
                                              float* __restrict__ out,
                                              float* __restrict__ st) {
    __shared__ float tile[80 * 84];
    __shared__ float ws[289];
    __shared__ float rs[8], rq[8];
    int c = blockIdx.y;
    int tb = blockIdx.x;
    int ty0 = (tb / 3) * 64, tx0 = (tb % 3) * 64;
    int tid = threadIdx.x;
    const float* Lc = L + (size_t)c * N_;
    for (int idx = tid; idx < 80 * 80; idx += 256) {
        int r = idx / 80, col = idx - r * 80;
        int gy = ty0 - 8 + r, gx = tx0 - 8 + col;
        float v = 0.f;
        if ((unsigned)gy < (unsigned)H_ && (unsigned)gx < (unsigned)W_) v = leaky(Lc[gy * W_ + gx]);
        tile[r * 84 + col] = v;
    }
    for (int idx = tid; idx < 289; idx += 256) ws[idx] = w0[c * 289 + idx];
    __syncthreads();

    int oy = tid >> 2;
    int ox = (tid & 3) * 16;
    float acc[16];
#pragma unroll
    for (int j = 0; j < 16; j++) acc[j] = 0.f;
    for (int ky = 0; ky < 17; ky++) {
        const float4* trow4 = reinterpret_cast<const float4*>(&tile[(oy + ky) * 84 + ox]);
        float row[32];
#pragma unroll
        for (int i = 0; i < 8; i++) {
            float4 v = trow4[i];
            row[4 * i] = v.x; row[4 * i + 1] = v.y; row[4 * i + 2] = v.z; row[4 * i + 3] = v.w;
        }
        const float* wr = &ws[ky * 17];
#pragma unroll
        for (int kx = 0; kx < 17; kx++) {
            float w = wr[kx];
#pragma unroll
            for (int j = 0; j < 16; j++) acc[j] += w * row[kx + j];
        }
    }
    float* op = out + (size_t)c * N_ + (ty0 + oy) * W_ + tx0 + ox;
#pragma unroll
    for (int j = 0; j < 4; j++)
        *reinterpret_cast<float4*>(op + 4 * j) =
            make_float4(acc[4 * j], acc[4 * j + 1], acc[4 * j + 2], acc[4 * j + 3]);

    float s = 0.f, q = 0.f;
#pragma unroll
    for (int j = 0; j < 16; j++) { s += acc[j]; q += acc[j] * acc[j]; }
#pragma unroll
    for (int off = 16; off > 0; off >>= 1) {
        s += __shfl_xor_sync(0xffffffffu, s, off);
        q += __shfl_xor_sync(0xffffffffu, q, off);
    }
    if ((tid & 31) == 0) { rs[tid >> 5] = s; rq[tid >> 5] = q; }
    __syncthreads();
    if (tid == 0) {
        float S = 0.f, Q = 0.f;
#pragma unroll
        for (int i = 0; i < 8; i++) { S += rs[i]; Q += rq[i]; }
        atomicAdd(&st[2 * c], S);
        atomicAdd(&st[2 * c + 1], Q);
    }
}

// ======================= depthwise 3x3 x4 (bf16 hi/lo out + stats fused) ======
__global__ __launch_bounds__(256) void k_dw3(const float* __restrict__ L,
                                             const float* __restrict__ w,
                                             __nv_bfloat16* __restrict__ oh,
                                             __nv_bfloat16* __restrict__ ol,
                                             float* __restrict__ st) {
    __shared__ float tile[34 * 35];
    __shared__ float ws[36];
    int c = blockIdx.y;
    int tb = blockIdx.x;
    int ty0 = (tb / 6) * 32, tx0 = (tb % 6) * 32;
    int tid = threadIdx.x;
    const float* Lc = L + (size_t)c * N_;
    for (int idx = tid; idx < 34 * 34; idx += 256) {
        int r = idx / 34, col = idx - r * 34;
        int gy = ty0 - 1 + r, gx = tx0 - 1 + col;
        float v = 0.f;
        if ((unsigned)gy < (unsigned)H_ && (unsigned)gx < (unsigned)W_) v = leaky(Lc[gy * W_ + gx]);
        tile[r * 35 + col] = v;
    }
    if (tid < 36) ws[tid] = w[c * 36 + tid];
    __syncthreads();

    int oy = tid >> 3;
    int ox = (tid & 7) * 4;
    float acc[4][4];
#pragma unroll
    for (int j = 0; j < 4; j++)
#pragma unroll
        for (int q = 0; q < 4; q++) acc[j][q] = 0.f;
    for (int ky = 0; ky < 3; ky++) {
        const float* trow = &tile[(oy + ky) * 35 + ox];
        float row[6];
#pragma unroll
        for (int i = 0; i < 6; i++) row[i] = trow[i];
#pragma unroll
        for (int kx = 0; kx < 3; kx++) {
#pragma unroll
            for (int j = 0; j < 4; j++) {
                float wv = ws[j * 9 + ky * 3 + kx];
                acc[j][0] += wv * row[kx];
                acc[j][1] += wv * row[kx + 1];
                acc[j][2] += wv * row[kx + 2];
                acc[j][3] += wv * row[kx + 3];
            }
        }
    }
    int p = (ty0 + oy) * W_ + tx0 + ox;
#pragma unroll
    for (int j = 0; j < 4; j++) {
        size_t base = (size_t)(c * 4 + j) * N_ + p;
        __nv_bfloat16 h0 = __float2bfloat16(acc[j][0]);
        __nv_bfloat16 h1 = __float2bfloat16(acc[j][1]);
        __nv_bfloat16 h2 = __float2bfloat16(acc[j][2]);
        __nv_bfloat16 h3 = __float2bfloat16(acc[j][3]);
        reinterpret_cast<__nv_bfloat162*>(oh + base)[0] = __nv_bfloat162(h0, h1);
        reinterpret_cast<__nv_bfloat162*>(oh + base)[1] = __nv_bfloat162(h2, h3);
        __nv_bfloat16 l0 = __float2bfloat16(acc[j][0] - __bfloat162float(h0));
        __nv_bfloat16 l1 = __float2bfloat16(acc[j][1] - __bfloat162float(h1));
        __nv_bfloat16 l2 = __float2bfloat16(acc[j][2] - __bfloat162float(h2));
        __nv_bfloat16 l3 = __float2bfloat16(acc[j][3] - __bfloat162float(h3));
        reinterpret_cast<__nv_bfloat162*>(ol + base)[0] = __nv_bfloat162(l0, l1);
        reinterpret_cast<__nv_bfloat162*>(ol + base)[1] = __nv_bfloat162(l2, l3);
    }
#pragma unroll
    for (int j = 0; j < 4; j++) {
        float s = acc[j][0] + acc[j][1] + acc[j][2] + acc[j][3];
        float q = acc[j][0] * acc[j][0] + acc[j][1] * acc[j][1]
                + acc[j][2] * acc[j][2] + acc[j][3] * acc[j][3];
#pragma unroll
        for (int off = 16; off > 0; off >>= 1) {
            s += __shfl_xor_sync(0xffffffffu, s, off);
            q += __shfl_xor_sync(0xffffffffu, q, off);
        }
        if ((tid & 31) == 0) {
            atomicAdd(&st[2 * (c * 4 + j)], s);
            atomicAdd(&st[2 * (c * 4 + j) + 1], q);
        }
    }
}

// ======================= edge stage (fused) =======================
__global__ void k_detect(const int* __restrict__ info32) {
    if (blockIdx.x == 0 && threadIdx.x == 0) {
        long long s = 0;
        for (int i = 1; i < 256; i += 2) {
            int v = info32[i];
            s += (v < 0) ? -(long long)v : (long long)v;
        }
        g_is64 = (s == 0) ? 1 : 0;
    }
}
__device__ __forceinline__ void load_edge(const void* info, int e, int& src, int& k1, int& dst, int& k2) {
    if (g_is64) {
        const long long* q = reinterpret_cast<const long long*>(info) + (size_t)e * 4;
        src = (int)q[0]; k1 = (int)q[1]; dst = (int)q[2]; k2 = (int)q[3];
    } else {
        const int* q = reinterpret_cast<const int*>(info) + (size_t)e * 4;
        src = q[0]; k1 = q[1]; dst = q[2]; k2 = q[3];
    }
}
__global__ void k_edge(const void* __restrict__ info, const float* __restrict__ msk) {
    int w = (blockIdx.x * blockDim.x + threadIdx.x) >> 5;
    int lane = threadIdx.x & 31;
    if (w >= E_) return;
    int src = 0, dst = 0;
    float a = 0.f;
    if (lane == 0) {
        int k1, k2;
        load_edge(info, w, src, k1, dst, k2);
        float mk = msk[w];
        if (mk != 0.f) {
            float s = g_sig[(size_t)k1 * N_ + src] + g_sig[(size_t)k2 * N_ + dst];
            s = fminf(fmaxf(s, -5.f), 5.f);
            a = expf(s) * mk;
        }
        if (a != 0.f) atomicAdd(&g_asum[dst], a);
    }
    a = __shfl_sync(0xffffffffu, a, 0);
    if (a == 0.f) return;
    src = __shfl_sync(0xffffffffu, src, 0);
    dst = __shfl_sync(0xffffffffu, dst, 0);
    const float4* xs = reinterpret_cast<const float4*>(g_xn + (size_t)src * C_);
    float* xd = g_xa + (size_t)dst * C_;
#pragma unroll
    for (int i = 0; i < 2; i++) {
        int c4 = lane + 32 * i;
        float4 v = xs[c4];
        red_v4(xd + c4 * 4, v.x * a, v.y * a, v.z * a, v.w * a);
    }
}
__global__ void k_xtrans_stats(float* __restrict__ st) {
    int c = blockIdx.x * 32 + threadIdx.x;
    int ty = threadIdx.y;
    float s = 0.f, s2 = 0.f;
    for (int n = blockIdx.y * 8 + ty; n < N_; n += gridDim.y * 8) {
        float d = g_asum[n] + 1e-5f;
        size_t idx = (size_t)n * C_ + c;
        float v = g_xa[idx] / d;
        g_xa[idx] = v;
        s += v; s2 += v * v;
    }
    __shared__ float sh[8][32], sh2[8][32];
    sh[ty][threadIdx.x] = s; sh2[ty][threadIdx.x] = s2;
    __syncthreads();
    if (ty == 0) {
#pragma unroll
        for (int i = 1; i < 8; i++) { s += sh[i][threadIdx.x]; s2 += sh2[i][threadIdx.x]; }
        atomicAdd(&st[2 * c], s);
        atomicAdd(&st[2 * c + 1], s2);
    }
}
__global__ void k_bn1d_add(const float* __restrict__ gm, const float* __restrict__ bt,
                           const float* __restrict__ st) {
    __shared__ float tile[32][33];
    int nb = blockIdx.x * 32, cb = blockIdx.y * 32;
    int tx = threadIdx.x, ty = threadIdx.y;
#pragma unroll
    for (int i = 0; i < 32; i += 8)
        tile[ty + i][tx] = g_xa[(size_t)(nb + ty + i) * C_ + cb + tx];
    __syncthreads();
#pragma unroll
    for (int i = 0; i < 32; i += 8) {
        int c = cb + ty + i;
        float m  = st[2 * c] * (1.f / N_);
        float vr = st[2 * c + 1] * (1.f / N_) - m * m;
        float rs = rsqrtf(vr + 1e-5f);
        float sc = rs * gm[c];
        float sb = bt[c] - m * sc;
        g_img[(size_t)c * N_ + nb + tx] += tile[tx][ty + i] * sc + sb;
    }
}
__global__ void k_final(const float* __restrict__ gm, const float* __restrict__ bt,
                        const float* __restrict__ st, float* __restrict__ out) {
    __shared__ float tile[32][33];
    int nb = blockIdx.x * 32, cb = blockIdx.y * 32;
    int tx = threadIdx.x, ty = threadIdx.y;
#pragma unroll
    for (int i = 0; i < 32; i += 8) {
        int c = cb + ty + i;
        float m  = st[2 * c] * (1.f / N_);
        float vr = st[2 * c + 1] * (1.f / N_) - m * m;
        float rs = rsqrtf(vr + 1e-5f);
        float sc = rs * gm[c];
        float sb = bt[c] - m * sc;
        size_t idx = (size_t)c * N_ + nb + tx;
        tile[ty + i][tx] = g_t2[idx] * sc + sb + g_img[idx];
    }
    __syncthreads();
#pragma unroll
    for (int i = 0; i < 32; i += 8)
        out[(size_t)(nb + ty + i) * C_ + cb + tx] = tile[tx][ty + i];
}

// ======================= host orchestration =======================
extern "C" void kernel_launch(void* const* d_in, const int* in_sizes, int n_in,
                              void* d_out, int out_size) {
    const float* X       = (const float*)d_in[0];
    const void*  info    = d_in[1];
    const float* msk     = (const float*)d_in[2];
    const float* ppm_w0  = (const float*)d_in[3];
    const float* ppm_g0  = (const float*)d_in[4];
    const float* ppm_b0  = (const float*)d_in[5];
    const float* ppm_w1  = (const float*)d_in[6];
    const float* ppm_g1  = (const float*)d_in[7];
    const float* ppm_b1  = (const float*)d_in[8];
    const float* ffn1_w0 = (const float*)d_in[9];
    const float* ffn1_g0 = (const float*)d_in[10];
    const float* ffn1_b0 = (const float*)d_in[11];
    const float* ffn1_w1 = (const float*)d_in[12];
    const float* ffn1_g1 = (const float*)d_in[13];
    const float* ffn1_b1 = (const float*)d_in[14];
    const float* dis_w1  = (const float*)d_in[15];
    const float* dis_b1  = (const float*)d_in[16];
    const float* dis_w2  = (const float*)d_in[17];
    const float* dis_b2  = (const float*)d_in[18];
    const float* bn_g    = (const float*)d_in[19];
    const float* bn_b    = (const float*)d_in[20];
    const float* ffn2_w0 = (const float*)d_in[21];
    const float* ffn2_g0 = (const float*)d_in[22];
    const float* ffn2_b0 = (const float*)d_in[23];
    const float* ffn2_w1 = (const float*)d_in[24];
    const float* ffn2_g1 = (const float*)d_in[25];
    const float* ffn2_b1 = (const float*)d_in[26];
    float* out = (float*)d_out;

    float *img, *tb, *t2, *big, *sig, *xn, *xa, *asum, *stats;
    __nv_bfloat16 *ahi, *alo, *whi, *wlo;
    cudaGetSymbolAddress((void**)&img,   g_img);
    cudaGetSymbolAddress((void**)&tb,    g_tb);
    cudaGetSymbolAddress((void**)&t2,    g_t2);
    cudaGetSymbolAddress((void**)&big,   g_big);
    cudaGetSymbolAddress((void**)&sig,   g_sig);
    cudaGetSymbolAddress((void**)&xn,    g_xn);
    cudaGetSymbolAddress((void**)&xa,    g_xa);
    cudaGetSymbolAddress((void**)&asum,  g_asum);
    cudaGetSymbolAddress((void**)&stats, g_stats);
    cudaGetSymbolAddress((void**)&ahi,   g_ahi);
    cudaGetSymbolAddress((void**)&alo,   g_alo);
    cudaGetSymbolAddress((void**)&whi,   g_whi);
    cudaGetSymbolAddress((void**)&wlo,   g_wlo);
    __nv_bfloat16* bigh = (__nv_bfloat16*)big;
    __nv_bfloat16* bigl = bigh + (size_t)C4_ * N_;

    static bool attr_done = false;
    if (!attr_done) {
        cudaFuncSetAttribute(k_gemm_mma, cudaFuncAttributeMaxDynamicSharedMemorySize, G_SMEM_TOTAL);
        attr_done = true;
    }

    float* st0 = stats + 0 * 2048;   // dw17 out
    float* st1 = stats + 1 * 2048;   // ppm1 gemm out
    float* st2 = stats + 2 * 2048;   // f1w0 gemm out
    float* st3 = stats + 3 * 2048;   // f1w1 gemm out
    float* st4 = stats + 4 * 2048;   // x_trans
    float* st5 = stats + 5 * 2048;   // dw3 out
    float* st6 = stats + 6 * 2048;   // f2w1 gemm out

    dim3 b32x8(32, 8);
    dim3 gT(N_ / 32, C_ / 32);
    dim3 gS(N_ / 32, 4);
    dim3 gStat(C_, 4);

    auto gemm = [&](int woff, const float* bias, float* Y,
                    int M, int Mpad, int Kc, int BIAS, int OUTLK) {
        k_gemm_mma<<<dim3(N_ / 128, Mpad / 128), 256, G_SMEM_TOTAL>>>(
            whi + woff, wlo + woff, ahi, alo, bias, Y, M, Kc, BIAS, OUTLK);
    };

    // launches 0-3
    k_detect<<<1, 32>>>((const int*)info);
    k_zero<<<16, 256>>>(stats, 7 * 2048);
    k_nm2cm<<<gT, b32x8>>>(X, img);
    k_dw17<<<dim3(9, C_), 256>>>(img, ppm_w0, tb, st0);
    // remaining setup
    k_wsplit6<<<dim3(96, 6), 256>>>(ppm_w1, ffn1_w0, ffn1_w1, dis_w1, dis_w2, ffn2_w1);
    k_zero<<<36, 256>>>(asum, N_);
    k_zero4<<<(N_ * C_ / 4 + 255) / 256, 256>>>((float4*)xa, N_ * C_ / 4);

    // ---- PPM ----
    k_split<<<gS, b32x8>>>(tb, ppm_g0, ppm_b0, st0, ahi, alo, nullptr, C_, 3);
    gemm(WOFF_PPM1, nullptr, t2, 256, 256, 256, 0, 0);
    k_stats<<<gStat, 256>>>(t2, st1);
    k_bnadd_split<<<gS, b32x8>>>(t2, img, ppm_g1, ppm_b1, st1, ahi, alo, nullptr, 1);

    // ---- FFN1 ----
    gemm(WOFF_F1W0, nullptr, tb, 256, 256, 256, 0, 0);
    k_stats<<<gStat, 256>>>(tb, st2);
    k_split<<<gS, b32x8>>>(tb, ffn1_g0, ffn1_b0, st2, ahi, alo, nullptr, C_, 3);
    gemm(WOFF_F1W1, nullptr, t2, 256, 256, 256, 0, 0);
    k_stats<<<gStat, 256>>>(t2, st3);
    k_bnadd_split<<<gS, b32x8>>>(t2, img, ffn1_g1, ffn1_b1, st3, ahi, alo, xn, 0);

    // ---- discriminator / graph attention ----
    gemm(WOFF_DIS1, dis_b1, tb, 256, 256, 256, 1, 1);
    k_split<<<gS, b32x8>>>(tb, nullptr, nullptr, nullptr, ahi, alo, nullptr, C_, 0);
    gemm(WOFF_DIS2, dis_b2, sig, 289, 384, 256, 1, 0);
    k_edge<<<E_ / 8, 256>>>(info, msk);
    k_xtrans_stats<<<dim3(8, 64), b32x8>>>(st4);
    k_bn1d_add<<<gT, b32x8>>>(bn_g, bn_b, st4);

    // ---- FFN2 ----
    k_dw3<<<dim3(36, C_), 256>>>(img, ffn2_w0, bigh, bigl, st5);
    k_split_b<<<dim3(N_ / 32, C4_ / 64), b32x8>>>(bigh, bigl, ffn2_g0, ffn2_b0, st5, ahi, alo);
    gemm(WOFF_F2W1, nullptr, t2, 256, 256, 1024, 0, 0);
    k_stats<<<gStat, 256>>>(t2, st6);
    k_final<<<gT, b32x8>>>(ffn2_g1, ffn2_b1, st6, out);

    (void)in_sizes; (void)n_in; (void)out_size;
}